// round 12
// baseline (speedup 1.0000x reference)
#include <cuda_runtime.h>
#include <math.h>

#define EPSF 1e-8f
#define LAMF 1e-3f

// ---------------- packed f32x2 helpers (Blackwell) ----------------
typedef unsigned long long u64t;
__device__ __forceinline__ u64t f2pack(float lo, float hi) {
    u64t r; asm("mov.b64 %0, {%1, %2};" : "=l"(r) : "f"(lo), "f"(hi)); return r;
}
__device__ __forceinline__ float2 f2unpack(u64t v) {
    float2 f; asm("mov.b64 {%0, %1}, %2;" : "=f"(f.x), "=f"(f.y) : "l"(v)); return f;
}
__device__ __forceinline__ u64t f2fma(u64t a, u64t b, u64t c) {
    u64t d; asm("fma.rn.f32x2 %0, %1, %2, %3;" : "=l"(d) : "l"(a), "l"(b), "l"(c)); return d;
}
__device__ __forceinline__ u64t f2mul(u64t a, u64t b) {
    u64t d; asm("mul.rn.f32x2 %0, %1, %2;" : "=l"(d) : "l"(a), "l"(b)); return d;
}
__device__ __forceinline__ u64t f2add(u64t a, u64t b) {
    u64t d; asm("add.rn.f32x2 %0, %1, %2;" : "=l"(d) : "l"(a), "l"(b)); return d;
}

// ---------------- static device scratch ----------------
__device__ float d_pose_prim[64 * 16 * 16 * 128];  // (b,h,w,8,16)
__device__ float d_a_prim[64 * 16 * 16 * 8];       // (b,h,w,8)
__device__ float d_pose1[64 * 7 * 7 * 16 * 16];
__device__ float d_a1[64 * 7 * 7 * 16];
__device__ float d_pose2[64 * 5 * 5 * 16 * 16];
__device__ float d_a2[64 * 5 * 5 * 16];
__device__ float d_vbuf[4096000];                  // class votes only

// =====================================================================
// fused conv5x5s2 + BN + ReLU + primary caps
// =====================================================================
__global__ void __launch_bounds__(256) convprim_kernel(
    const float* __restrict__ x, const float* __restrict__ w,
    const float* __restrict__ bconv, const float* __restrict__ g,
    const float* __restrict__ bb, const float* __restrict__ mean,
    const float* __restrict__ var,
    const float* __restrict__ pw, const float* __restrict__ pb,
    const float* __restrict__ aw, const float* __restrict__ ab)
{
    __shared__ float xs[160];
    __shared__ float wconv[1600];
    __shared__ __align__(16) float yv[1024];
    __shared__ __align__(16) float wp_s[128 * 68];
    __shared__ __align__(16) float wa_s[8 * 68];
    __shared__ float bnsc[64], bnbi[64];

    const int tid = threadIdx.x;
    const int blk = blockIdx.x;
    const int b = blk >> 4, oh = blk & 15;

    for (int t = tid; t < 160; t += 256) {
        int kh = t >> 5, iw = t & 31;
        int ih = oh * 2 - 2 + kh;
        xs[t] = (ih >= 0 && ih < 32) ? x[b * 1024 + ih * 32 + iw] : 0.0f;
    }
    for (int t = tid; t < 1600; t += 256) wconv[t] = w[t];
    for (int t = tid; t < 128 * 64; t += 256) {
        int o = t >> 6, c = t & 63;
        wp_s[o * 68 + c] = pw[t];
    }
    for (int t = tid; t < 8 * 64; t += 256) {
        int o = t >> 6, c = t & 63;
        wa_s[o * 68 + c] = aw[t];
    }
    if (tid < 64) {
        float sc = g[tid] * rsqrtf(var[tid] + 1e-3f);
        bnsc[tid] = sc;
        bnbi[tid] = bb[tid] - mean[tid] * sc;
    }
    __syncthreads();

    for (int t = tid; t < 1024; t += 256) {
        int co = t & 63, ow = t >> 6;
        float acc = bconv[co];
        const float* wr = wconv + co * 25;
#pragma unroll
        for (int kh = 0; kh < 5; kh++) {
#pragma unroll
            for (int kw = 0; kw < 5; kw++) {
                int iw = ow * 2 - 2 + kw;
                if (iw >= 0 && iw < 32)
                    acc += xs[kh * 32 + iw] * wr[kh * 5 + kw];
            }
        }
        yv[ow * 64 + co] = fmaxf(acc * bnsc[co] + bnbi[co], 0.0f);
    }
    __syncthreads();

    for (int t = tid; t < 16 * 136; t += 256) {
        int pos = t / 136, o = t % 136;
        const float4* y4 = (const float4*)(yv + pos * 64);
        int pg = (blk << 4) + pos;
        if (o < 128) {
            const float4* w4 = (const float4*)(wp_s + o * 68);
            float4 a4 = make_float4(0.f, 0.f, 0.f, 0.f);
#pragma unroll
            for (int j = 0; j < 16; j++) {
                float4 yy = y4[j], ww = w4[j];
                a4.x += yy.x * ww.x; a4.y += yy.y * ww.y;
                a4.z += yy.z * ww.z; a4.w += yy.w * ww.w;
            }
            d_pose_prim[pg * 128 + o] = pb[o] + a4.x + a4.y + a4.z + a4.w;
        } else {
            int o2 = o - 128;
            const float4* w4 = (const float4*)(wa_s + o2 * 68);
            float4 a4 = make_float4(0.f, 0.f, 0.f, 0.f);
#pragma unroll
            for (int j = 0; j < 16; j++) {
                float4 yy = y4[j], ww = w4[j];
                a4.x += yy.x * ww.x; a4.y += yy.y * ww.y;
                a4.z += yy.z * ww.z; a4.w += yy.w * ww.w;
            }
            float acc = ab[o2] + a4.x + a4.y + a4.z + a4.w;
            d_a_prim[pg * 8 + o2] = 1.0f / (1.0f + expf(-acc));
        }
    }
}

// vote recompute: packed (x,y),(z,w) from pp (smem) + W row (L1-hot)
__device__ __forceinline__ void vote_f2(
    const float4* __restrict__ pp4, const ulonglong2* __restrict__ W2,
    int i, int gc, int gp, int C, u64t& oxy, u64t& ozw)
{
    float4 pv = pp4[i * 4 + gp];
    u64t p0 = f2pack(pv.x, pv.x);
    u64t p1 = f2pack(pv.y, pv.y);
    u64t p2 = f2pack(pv.z, pv.z);
    u64t p3 = f2pack(pv.w, pv.w);
    const ulonglong2* wr = W2 + (size_t)(i * C + gc) * 4;
    ulonglong2 q0 = wr[0], q1 = wr[1], q2 = wr[2], q3 = wr[3];
    oxy = f2mul(p0, q0.x);
    oxy = f2fma(p1, q1.x, oxy);
    oxy = f2fma(p2, q2.x, oxy);
    oxy = f2fma(p3, q3.x, oxy);
    ozw = f2mul(p0, q0.y);
    ozw = f2fma(p1, q1.y, ozw);
    ozw = f2fma(p2, q2.y, ozw);
    ozw = f2fma(p3, q3.y, ozw);
}

// =====================================================================
// conv caps layer: votes RECOMPUTED each pass (low regs -> 2 blocks/SM)
// =====================================================================
template <int N, int Bi, int C, int OHW, int IHW, int STRIDE>
__global__ void __launch_bounds__(512, 2) caps_kernel(
    const float* __restrict__ pose_in, const float* __restrict__ a_in,
    const float* __restrict__ W, const float* __restrict__ bu,
    const float* __restrict__ ba,
    float* __restrict__ pose_out, float* __restrict__ a_out_g)
{
    static_assert(C == 16, "caps path assumes C==16");
    constexpr int THREADS = 512;
    constexpr int CP = 256;
    constexpr int REPS4 = 8;
    constexpr int ITER = N / REPS4;
    static_assert(N % REPS4 == 0, "N divisible");

    __shared__ __align__(16) float pp[N * 16];
    __shared__ float a[N];
    __shared__ float wa[N];
    __shared__ float r[N * C];
    __shared__ __align__(16) float mu[CP];
    __shared__ float sig[CP];
    __shared__ __align__(16) float part[2 * REPS4 * CP];
    __shared__ float colsum[C];
    __shared__ float invcol[C];
    __shared__ float sA;

    const int tid = threadIdx.x;
    const int n = blockIdx.x;
    const int b = n / (OHW * OHW);
    const int rem = n % (OHW * OHW);
    const int oh = rem / OHW, ow = rem % OHW;

    {
        float4* pp4s = (float4*)pp;
        for (int idx = tid; idx < N * 4; idx += THREADS) {
            int i = idx >> 2, q = idx & 3;
            int kh = i / (3 * Bi), kw = (i / Bi) % 3, bi = i % Bi;
            int ih = oh * STRIDE + kh, iw = ow * STRIDE + kw;
            pp4s[idx] = ((const float4*)pose_in)[(((b * IHW + ih) * IHW + iw) * Bi + bi) * 4 + q];
        }
    }
    for (int i = tid; i < N; i += THREADS) {
        int kh = i / (3 * Bi), kw = (i / Bi) % 3, bi = i % Bi;
        int ih = oh * STRIDE + kh, iw = ow * STRIDE + kw;
        a[i] = a_in[((b * IHW + ih) * IHW + iw) * Bi + bi];
    }
    __syncthreads();

    if (tid < 32) {
        float s = 0.f;
        for (int i = tid; i < N; i += 32) s += a[i];
#pragma unroll
        for (int o = 16; o; o >>= 1) s += __shfl_xor_sync(0xffffffffu, s, o);
        if (tid == 0) sA = s;
    }
    __syncthreads();
    {
        float denom = sA + EPSF * (float)(C * C);
        for (int i = tid; i < N; i += THREADS) wa[i] = a[i] / denom;
    }
    __syncthreads();

    const int g = tid & 63, rep = tid >> 6;
    const int gc = g >> 2, gp = g & 3;
    const float4* pp4 = (const float4*)pp;
    const ulonglong2* W2 = (const ulonglong2*)W;

    // ---- pass 1: votes + mu0 partials (no vote storage)
    {
        u64t accx = 0, accz = 0;
#pragma unroll
        for (int it = 0; it < ITER; it++) {
            int i = rep + it * REPS4;
            u64t oxy, ozw;
            vote_f2(pp4, W2, i, gc, gp, C, oxy, ozw);
            u64t wi2 = f2pack(wa[i], wa[i]);
            accx = f2fma(wi2, oxy, accx);
            accz = f2fma(wi2, ozw, accz);
        }
        ((ulonglong2*)part)[rep * 64 + g] = make_ulonglong2(accx, accz);
    }
    __syncthreads();
    if (tid < CP) {
        float s = 0.f;
#pragma unroll
        for (int rr = 0; rr < REPS4; rr++) s += part[rr * CP + tid];
        mu[tid] = s;
    }
    __syncthreads();

    // ---- pass 2: recompute votes, dist -> inv
    {
        float4 mm = ((const float4*)mu)[gc * 4 + gp];
        u64t nmx = f2pack(-mm.x, -mm.y);
        u64t nmz = f2pack(-mm.z, -mm.w);
#pragma unroll
        for (int it = 0; it < ITER; it++) {
            int i = rep + it * REPS4;
            u64t oxy, ozw;
            vote_f2(pp4, W2, i, gc, gp, C, oxy, ozw);
            u64t t1 = f2add(oxy, nmx);
            u64t t2 = f2add(ozw, nmz);
            u64t u = f2fma(t2, t2, f2mul(t1, t1));
            float2 uf = f2unpack(u);
            float d = uf.x + uf.y;
            d += __shfl_xor_sync(0xffffffffu, d, 1);
            d += __shfl_xor_sync(0xffffffffu, d, 2);
            if (gp == 0) r[i * C + gc] = 1.0f / (d + EPSF);
        }
    }
    __syncthreads();

    // ---- rowsum over C via 16-lane shuffle
    for (int t = tid; t < N * 16; t += THREADS) {
        int i = t >> 4, c = t & 15;
        float s = r[i * 16 + c];
        s += __shfl_xor_sync(0xffffffffu, s, 1);
        s += __shfl_xor_sync(0xffffffffu, s, 2);
        s += __shfl_xor_sync(0xffffffffu, s, 4);
        s += __shfl_xor_sync(0xffffffffu, s, 8);
        if (c == 0) wa[i] = 1.0f / (s + EPSF);
    }
    __syncthreads();

    // ---- fused coeff^2*a + colsum partials
    for (int t = tid; t < 32 * C; t += THREADS) {
        int sub = t >> 4, c = t & 15;
        float s = 0.f;
        for (int i = sub; i < N; i += 32) {
            float val = r[i * C + c] * wa[i];
            val = val * val * a[i];
            r[i * C + c] = val;
            s += val;
        }
        part[t] = s;
    }
    __syncthreads();
    if (tid < C) {
        float s = 0.f;
#pragma unroll
        for (int sub = 0; sub < 32; sub++) s += part[sub * C + tid];
        colsum[tid] = s;
        invcol[tid] = 1.0f / (s + EPSF);
    }
    __syncthreads();

    // ---- pass 3: recompute votes, fused S1/S2 (normalize on the fly)
    {
        float icn = invcol[gc];
        u64t s1x = 0, s1z = 0, s2x = 0, s2z = 0;
#pragma unroll
        for (int it = 0; it < ITER; it++) {
            int i = rep + it * REPS4;
            u64t oxy, ozw;
            vote_f2(pp4, W2, i, gc, gp, C, oxy, ozw);
            float cf = r[i * C + gc] * icn;
            u64t cf2 = f2pack(cf, cf);
            s1x = f2fma(cf2, oxy, s1x);
            s1z = f2fma(cf2, ozw, s1z);
            s2x = f2fma(cf2, f2mul(oxy, oxy), s2x);
            s2z = f2fma(cf2, f2mul(ozw, ozw), s2z);
        }
        ((ulonglong2*)part)[rep * 64 + g] = make_ulonglong2(s1x, s1z);
        ((ulonglong2*)part)[(REPS4 + rep) * 64 + g] = make_ulonglong2(s2x, s2z);
    }
    __syncthreads();
    if (tid < CP) {
        float s1 = 0.f, s2 = 0.f;
#pragma unroll
        for (int rr = 0; rr < REPS4; rr++) {
            s1 += part[rr * CP + tid];
            s2 += part[(REPS4 + rr) * CP + tid];
        }
        mu[tid] = s1;
        float cs = colsum[tid >> 4];
        float rho = cs / (cs + EPSF);
        sig[tid] = fmaxf(s2 - s1 * s1 * (2.0f - rho), 0.0f) + EPSF;
    }
    __syncthreads();

    if (tid < C) {
        float ls = 0.f;
#pragma unroll
        for (int p = 0; p < 16; p++) ls += logf(sig[tid * 16 + p]);
        float cost = colsum[tid] * (16.0f * bu[tid] + 0.5f * ls);
        a_out_g[n * C + tid] = 1.0f / (1.0f + expf(-LAMF * (ba[tid] - cost)));
    }
    {
        float4* po4 = (float4*)(pose_out + (size_t)n * CP);
        for (int t = tid; t < 64; t += THREADS) po4[t] = ((const float4*)mu)[t];
    }
}

// =====================================================================
// class caps: votes+mu0 fused (fixed (c,p)-ownership), v in L2
// =====================================================================
__global__ void __launch_bounds__(1024) class_kernel(
    const float* __restrict__ wc, const float* __restrict__ buc,
    const float* __restrict__ bac, float* __restrict__ out)
{
    constexpr int N = 400, C = 10, CP = 160, T = 1024, REPS = 6;
    __shared__ float a[N];
    __shared__ float wa[N];
    __shared__ float r[N * C];
    __shared__ __align__(16) float mu[CP];
    __shared__ float sig[CP];
    __shared__ float part[2 * REPS * CP];
    __shared__ __align__(16) float partA[25 * CP];
    __shared__ float colsum[C];
    __shared__ float sA;

    const int b = blockIdx.x;
    const int tid = threadIdx.x;
    const float* pose = d_pose2 + (size_t)b * N * 16;
    float* v = d_vbuf + (size_t)b * N * C * 16;

    for (int i = tid; i < N; i += T) a[i] = d_a2[b * N + i];
    __syncthreads();

    if (tid < 32) {
        float s = 0.f;
        for (int i = tid; i < N; i += 32) s += a[i];
#pragma unroll
        for (int o = 16; o; o >>= 1) s += __shfl_xor_sync(0xffffffffu, s, o);
        if (tid == 0) sA = s;
    }
    __syncthreads();
    {
        float denom = sA + EPSF * (float)(C * C);
        for (int i = tid; i < N; i += T) wa[i] = a[i] / denom;
    }
    __syncthreads();

    {
        const int g = tid % 40, rep = tid / 40;
        if (rep < 25) {
            const int gc = g >> 2, gp = g & 3;
            float4 acc = make_float4(0.f, 0.f, 0.f, 0.f);
#pragma unroll
            for (int it = 0; it < 16; it++) {
                int i = rep + it * 25;
                float4 pv = ((const float4*)pose)[i * 4 + gp];
                const float4* wp4 = (const float4*)(wc + ((size_t)((i & 15) * 10 + gc)) * 16);
                float4 w0 = wp4[0], w1 = wp4[1], w2 = wp4[2], w3 = wp4[3];
                float4 o;
                o.x = pv.x * w0.x + pv.y * w1.x + pv.z * w2.x + pv.w * w3.x;
                o.y = pv.x * w0.y + pv.y * w1.y + pv.z * w2.y + pv.w * w3.y;
                o.z = pv.x * w0.z + pv.y * w1.z + pv.z * w2.z + pv.w * w3.z;
                o.w = pv.x * w0.w + pv.y * w1.w + pv.z * w2.w + pv.w * w3.w;
                if (gp == 0) {
                    o.x += (float)(i / 80) * 0.2f;
                    o.y += (float)((i / 16) % 5) * 0.2f;
                }
                *(float4*)(v + (i * C + gc) * 16 + gp * 4) = o;
                float wi = wa[i];
                acc.x += wi * o.x; acc.y += wi * o.y;
                acc.z += wi * o.z; acc.w += wi * o.w;
            }
            ((float4*)partA)[rep * 40 + g] = acc;
        }
    }
    __syncthreads();
    if (tid < CP) {
        float s = 0.f;
#pragma unroll
        for (int rr = 0; rr < 25; rr++) s += partA[rr * CP + tid];
        mu[tid] = s;
    }
    __syncthreads();

    for (int t = tid; t < N * C * 4; t += T) {
        int pair = t >> 2, ch = t & 3;
        int c = pair % C;
        float4 vv = *(const float4*)(v + pair * 16 + ch * 4);
        float4 mm = *(const float4*)(mu + c * 16 + ch * 4);
        float dx = vv.x - mm.x, dy = vv.y - mm.y, dz = vv.z - mm.z, dw = vv.w - mm.w;
        float d = dx * dx + dy * dy + dz * dz + dw * dw;
        d += __shfl_xor_sync(0xffffffffu, d, 1);
        d += __shfl_xor_sync(0xffffffffu, d, 2);
        if (ch == 0) r[pair] = 1.0f / (d + EPSF);
    }
    __syncthreads();

    for (int i = tid; i < N; i += T) {
        float s = 0.f;
#pragma unroll
        for (int c = 0; c < C; c++) s += r[i * C + c];
        wa[i] = 1.0f / (s + EPSF);
    }
    __syncthreads();

    for (int t = tid; t < N * C; t += T) {
        int i = t / C;
        float val = r[t] * wa[i];
        r[t] = val * val * a[i];
    }
    __syncthreads();

    for (int t = tid; t < 32 * C; t += T) {
        int sub = t / C, c = t % C;
        float s = 0.f;
        for (int i = sub; i < N; i += 32) s += r[i * C + c];
        part[t] = s;
    }
    __syncthreads();
    if (tid < C) {
        float s = 0.f;
#pragma unroll
        for (int sub = 0; sub < 32; sub++) s += part[sub * C + tid];
        colsum[tid] = s;
    }
    __syncthreads();

    for (int t = tid; t < N * C; t += T) r[t] /= (colsum[t % C] + EPSF);
    __syncthreads();

    {
        int rep = tid / CP, t2 = tid % CP;
        if (rep < REPS) {
            int c = t2 / 16, pr = t2 & 15;
            float s1 = 0.f, s2 = 0.f;
            for (int i = rep; i < N; i += REPS) {
                float cf = r[i * C + c];
                float vv = v[(i * C + c) * 16 + pr];
                s1 += cf * vv;
                s2 += cf * vv * vv;
            }
            part[rep * CP + t2] = s1;
            part[(REPS + rep) * CP + t2] = s2;
        }
    }
    __syncthreads();
    if (tid < CP) {
        float s1 = 0.f, s2 = 0.f;
#pragma unroll
        for (int rr = 0; rr < REPS; rr++) {
            s1 += part[rr * CP + tid];
            s2 += part[(REPS + rr) * CP + tid];
        }
        int c = tid / 16;
        float cs = colsum[c];
        float rho = cs / (cs + EPSF);
        sig[tid] = fmaxf(s2 - s1 * s1 * (2.0f - rho), 0.0f) + EPSF;
    }
    __syncthreads();

    if (tid < C) {
        float ls = 0.f;
#pragma unroll
        for (int p = 0; p < 16; p++) ls += logf(sig[tid * 16 + p]);
        float cost = colsum[tid] * (16.0f * buc[tid] + 0.5f * ls);
        out[b * C + tid] = 1.0f / (1.0f + expf(-LAMF * (bac[tid] - cost)));
    }
}

// ---------------- launch ----------------
extern "C" void kernel_launch(void* const* d_in, const int* in_sizes, int n_in,
                              void* d_out, int out_size)
{
    const float* x        = (const float*)d_in[0];
    const float* conv1_w  = (const float*)d_in[1];
    const float* conv1_b  = (const float*)d_in[2];
    const float* bn_g     = (const float*)d_in[3];
    const float* bn_b     = (const float*)d_in[4];
    const float* bn_mean  = (const float*)d_in[5];
    const float* bn_var   = (const float*)d_in[6];
    const float* ppose_w  = (const float*)d_in[7];
    const float* ppose_b  = (const float*)d_in[8];
    const float* pa_w     = (const float*)d_in[9];
    const float* pa_b     = (const float*)d_in[10];
    const float* w1       = (const float*)d_in[11];
    const float* bu1      = (const float*)d_in[12];
    const float* ba1      = (const float*)d_in[13];
    const float* w2       = (const float*)d_in[14];
    const float* bu2      = (const float*)d_in[15];
    const float* ba2      = (const float*)d_in[16];
    const float* wc       = (const float*)d_in[17];
    const float* buc      = (const float*)d_in[18];
    const float* bac      = (const float*)d_in[19];
    float* out = (float*)d_out;

    float *ppose, *aprim, *pose1, *a1, *pose2, *a2;
    cudaGetSymbolAddress((void**)&ppose, d_pose_prim);
    cudaGetSymbolAddress((void**)&aprim, d_a_prim);
    cudaGetSymbolAddress((void**)&pose1, d_pose1);
    cudaGetSymbolAddress((void**)&a1, d_a1);
    cudaGetSymbolAddress((void**)&pose2, d_pose2);
    cudaGetSymbolAddress((void**)&a2, d_a2);

    convprim_kernel<<<1024, 256>>>(x, conv1_w, conv1_b, bn_g, bn_b, bn_mean, bn_var,
                                   ppose_w, ppose_b, pa_w, pa_b);
    caps_kernel<72, 8, 16, 7, 16, 2><<<3136, 512>>>(
        ppose, aprim, w1, bu1, ba1, pose1, a1);
    caps_kernel<144, 16, 16, 5, 7, 1><<<1600, 512>>>(
        pose1, a1, w2, bu2, ba2, pose2, a2);
    class_kernel<<<64, 1024>>>(wc, buc, bac, out);
}

// round 14
// speedup vs baseline: 1.9609x; 1.9609x over previous
#include <cuda_runtime.h>
#include <math.h>

#define EPSF 1e-8f
#define LAMF 1e-3f

// ---------------- packed f32x2 helpers (Blackwell) ----------------
typedef unsigned long long u64t;
__device__ __forceinline__ u64t f2pack(float lo, float hi) {
    u64t r; asm("mov.b64 %0, {%1, %2};" : "=l"(r) : "f"(lo), "f"(hi)); return r;
}
__device__ __forceinline__ float2 f2unpack(u64t v) {
    float2 f; asm("mov.b64 {%0, %1}, %2;" : "=f"(f.x), "=f"(f.y) : "l"(v)); return f;
}
__device__ __forceinline__ u64t f2fma(u64t a, u64t b, u64t c) {
    u64t d; asm("fma.rn.f32x2 %0, %1, %2, %3;" : "=l"(d) : "l"(a), "l"(b), "l"(c)); return d;
}
__device__ __forceinline__ u64t f2mul(u64t a, u64t b) {
    u64t d; asm("mul.rn.f32x2 %0, %1, %2;" : "=l"(d) : "l"(a), "l"(b)); return d;
}
__device__ __forceinline__ u64t f2add(u64t a, u64t b) {
    u64t d; asm("add.rn.f32x2 %0, %1, %2;" : "=l"(d) : "l"(a), "l"(b)); return d;
}

// ---------------- static device scratch ----------------
__device__ float d_pose_prim[64 * 16 * 16 * 128];  // (b,h,w,8,16)
__device__ float d_a_prim[64 * 16 * 16 * 8];       // (b,h,w,8)
__device__ float d_pose1[64 * 7 * 7 * 16 * 16];
__device__ float d_a1[64 * 7 * 7 * 16];
__device__ float d_pose2[64 * 5 * 5 * 16 * 16];
__device__ float d_a2[64 * 5 * 5 * 16];
__device__ float d_vbuf[4096000];                  // class votes only

// =====================================================================
// fused conv5x5s2 + BN + ReLU + primary caps
// =====================================================================
__global__ void __launch_bounds__(256) convprim_kernel(
    const float* __restrict__ x, const float* __restrict__ w,
    const float* __restrict__ bconv, const float* __restrict__ g,
    const float* __restrict__ bb, const float* __restrict__ mean,
    const float* __restrict__ var,
    const float* __restrict__ pw, const float* __restrict__ pb,
    const float* __restrict__ aw, const float* __restrict__ ab)
{
    __shared__ float xs[160];
    __shared__ float wconv[1600];
    __shared__ __align__(16) float yv[1024];
    __shared__ __align__(16) float wp_s[128 * 68];
    __shared__ __align__(16) float wa_s[8 * 68];
    __shared__ float bnsc[64], bnbi[64];

    const int tid = threadIdx.x;
    const int blk = blockIdx.x;
    const int b = blk >> 4, oh = blk & 15;

    for (int t = tid; t < 160; t += 256) {
        int kh = t >> 5, iw = t & 31;
        int ih = oh * 2 - 2 + kh;
        xs[t] = (ih >= 0 && ih < 32) ? x[b * 1024 + ih * 32 + iw] : 0.0f;
    }
    for (int t = tid; t < 1600; t += 256) wconv[t] = w[t];
    for (int t = tid; t < 128 * 64; t += 256) {
        int o = t >> 6, c = t & 63;
        wp_s[o * 68 + c] = pw[t];
    }
    for (int t = tid; t < 8 * 64; t += 256) {
        int o = t >> 6, c = t & 63;
        wa_s[o * 68 + c] = aw[t];
    }
    if (tid < 64) {
        float sc = g[tid] * rsqrtf(var[tid] + 1e-3f);
        bnsc[tid] = sc;
        bnbi[tid] = bb[tid] - mean[tid] * sc;
    }
    __syncthreads();

    for (int t = tid; t < 1024; t += 256) {
        int co = t & 63, ow = t >> 6;
        float acc = bconv[co];
        const float* wr = wconv + co * 25;
#pragma unroll
        for (int kh = 0; kh < 5; kh++) {
#pragma unroll
            for (int kw = 0; kw < 5; kw++) {
                int iw = ow * 2 - 2 + kw;
                if (iw >= 0 && iw < 32)
                    acc += xs[kh * 32 + iw] * wr[kh * 5 + kw];
            }
        }
        yv[ow * 64 + co] = fmaxf(acc * bnsc[co] + bnbi[co], 0.0f);
    }
    __syncthreads();

    for (int t = tid; t < 16 * 136; t += 256) {
        int pos = t / 136, o = t % 136;
        const float4* y4 = (const float4*)(yv + pos * 64);
        int pg = (blk << 4) + pos;
        if (o < 128) {
            const float4* w4 = (const float4*)(wp_s + o * 68);
            float4 a4 = make_float4(0.f, 0.f, 0.f, 0.f);
#pragma unroll
            for (int j = 0; j < 16; j++) {
                float4 yy = y4[j], ww = w4[j];
                a4.x += yy.x * ww.x; a4.y += yy.y * ww.y;
                a4.z += yy.z * ww.z; a4.w += yy.w * ww.w;
            }
            d_pose_prim[pg * 128 + o] = pb[o] + a4.x + a4.y + a4.z + a4.w;
        } else {
            int o2 = o - 128;
            const float4* w4 = (const float4*)(wa_s + o2 * 68);
            float4 a4 = make_float4(0.f, 0.f, 0.f, 0.f);
#pragma unroll
            for (int j = 0; j < 16; j++) {
                float4 yy = y4[j], ww = w4[j];
                a4.x += yy.x * ww.x; a4.y += yy.y * ww.y;
                a4.z += yy.z * ww.z; a4.w += yy.w * ww.w;
            }
            float acc = ab[o2] + a4.x + a4.y + a4.z + a4.w;
            d_a_prim[pg * 8 + o2] = 1.0f / (1.0f + expf(-acc));
        }
    }
}

// =====================================================================
// conv caps layer: register-resident votes, packed f32x2 math.
// 768 threads (REPS4=12) -> smaller vote slice/thread, 24 warps/SM.
// =====================================================================
template <int N, int Bi, int C, int OHW, int IHW, int STRIDE>
__global__ void __launch_bounds__(768) caps_kernel(
    const float* __restrict__ pose_in, const float* __restrict__ a_in,
    const float* __restrict__ W, const float* __restrict__ bu,
    const float* __restrict__ ba,
    float* __restrict__ pose_out, float* __restrict__ a_out_g)
{
    static_assert(C == 16, "caps path assumes C==16");
    constexpr int THREADS = 768;
    constexpr int CP = 256;
    constexpr int REPS4 = THREADS / 64;     // 12
    constexpr int ITER = N / REPS4;         // 6 (caps1) / 12 (caps2)
    static_assert(N % REPS4 == 0, "N divisible");

    __shared__ __align__(16) float pp[N * 16];
    __shared__ float a[N];
    __shared__ float wa[N];
    __shared__ float r[N * C];
    __shared__ __align__(16) float mu[CP];
    __shared__ float sig[CP];
    __shared__ __align__(16) float part[2 * REPS4 * CP];
    __shared__ float colsum[C];
    __shared__ float invcol[C];
    __shared__ float sA;

    const int tid = threadIdx.x;
    const int n = blockIdx.x;
    const int b = n / (OHW * OHW);
    const int rem = n % (OHW * OHW);
    const int oh = rem / OHW, ow = rem % OHW;

    {
        float4* pp4s = (float4*)pp;
        for (int idx = tid; idx < N * 4; idx += THREADS) {
            int i = idx >> 2, q = idx & 3;
            int kh = i / (3 * Bi), kw = (i / Bi) % 3, bi = i % Bi;
            int ih = oh * STRIDE + kh, iw = ow * STRIDE + kw;
            pp4s[idx] = ((const float4*)pose_in)[(((b * IHW + ih) * IHW + iw) * Bi + bi) * 4 + q];
        }
    }
    for (int i = tid; i < N; i += THREADS) {
        int kh = i / (3 * Bi), kw = (i / Bi) % 3, bi = i % Bi;
        int ih = oh * STRIDE + kh, iw = ow * STRIDE + kw;
        a[i] = a_in[((b * IHW + ih) * IHW + iw) * Bi + bi];
    }
    __syncthreads();

    if (tid < 32) {
        float s = 0.f;
        for (int i = tid; i < N; i += 32) s += a[i];
#pragma unroll
        for (int o = 16; o; o >>= 1) s += __shfl_xor_sync(0xffffffffu, s, o);
        if (tid == 0) sA = s;
    }
    __syncthreads();
    {
        float denom = sA + EPSF * (float)(C * C);
        for (int i = tid; i < N; i += THREADS) wa[i] = a[i] / denom;
    }
    __syncthreads();

    const int g = tid & 63, rep = tid >> 6;
    const int gc = g >> 2, gp = g & 3;

    u64t vx[ITER], vz[ITER];   // packed votes: (x,y) and (z,w)

    // ---- pass 1: votes (packed) + mu0 partials
    {
        const float4* pp4 = (const float4*)pp;
        const ulonglong2* W2 = (const ulonglong2*)W;
        u64t accx = 0, accz = 0;
#pragma unroll
        for (int it = 0; it < ITER; it++) {
            int i = rep + it * REPS4;
            float4 pv = pp4[i * 4 + gp];
            u64t p0 = f2pack(pv.x, pv.x);
            u64t p1 = f2pack(pv.y, pv.y);
            u64t p2 = f2pack(pv.z, pv.z);
            u64t p3 = f2pack(pv.w, pv.w);
            const ulonglong2* wr = W2 + (size_t)(i * C + gc) * 4;
            ulonglong2 q0 = wr[0], q1 = wr[1], q2 = wr[2], q3 = wr[3];
            u64t oxy = f2mul(p0, q0.x);
            oxy = f2fma(p1, q1.x, oxy);
            oxy = f2fma(p2, q2.x, oxy);
            oxy = f2fma(p3, q3.x, oxy);
            u64t ozw = f2mul(p0, q0.y);
            ozw = f2fma(p1, q1.y, ozw);
            ozw = f2fma(p2, q2.y, ozw);
            ozw = f2fma(p3, q3.y, ozw);
            vx[it] = oxy; vz[it] = ozw;
            u64t wi2 = f2pack(wa[i], wa[i]);
            accx = f2fma(wi2, oxy, accx);
            accz = f2fma(wi2, ozw, accz);
        }
        ((ulonglong2*)part)[rep * 64 + g] = make_ulonglong2(accx, accz);
    }
    __syncthreads();
    if (tid < CP) {
        float s = 0.f;
#pragma unroll
        for (int rr = 0; rr < REPS4; rr++) s += part[rr * CP + tid];
        mu[tid] = s;
    }
    __syncthreads();

    // ---- pass 2: dist -> inv (packed, from registers)
    {
        float4 mm = ((const float4*)mu)[gc * 4 + gp];
        u64t nmx = f2pack(-mm.x, -mm.y);
        u64t nmz = f2pack(-mm.z, -mm.w);
#pragma unroll
        for (int it = 0; it < ITER; it++) {
            int i = rep + it * REPS4;
            u64t t1 = f2add(vx[it], nmx);
            u64t t2 = f2add(vz[it], nmz);
            u64t u = f2fma(t2, t2, f2mul(t1, t1));
            float2 uf = f2unpack(u);
            float d = uf.x + uf.y;
            d += __shfl_xor_sync(0xffffffffu, d, 1);
            d += __shfl_xor_sync(0xffffffffu, d, 2);
            if (gp == 0) r[i * C + gc] = 1.0f / (d + EPSF);
        }
    }
    __syncthreads();

    // ---- rowsum over C via 16-lane shuffle
    for (int t = tid; t < N * 16; t += THREADS) {
        int i = t >> 4, c = t & 15;
        float s = r[i * 16 + c];
        s += __shfl_xor_sync(0xffffffffu, s, 1);
        s += __shfl_xor_sync(0xffffffffu, s, 2);
        s += __shfl_xor_sync(0xffffffffu, s, 4);
        s += __shfl_xor_sync(0xffffffffu, s, 8);
        if (c == 0) wa[i] = 1.0f / (s + EPSF);
    }
    __syncthreads();

    // ---- fused coeff^2*a + colsum partials
    for (int t = tid; t < 32 * C; t += THREADS) {
        int sub = t >> 4, c = t & 15;
        float s = 0.f;
        for (int i = sub; i < N; i += 32) {
            float val = r[i * C + c] * wa[i];
            val = val * val * a[i];
            r[i * C + c] = val;
            s += val;
        }
        part[t] = s;
    }
    __syncthreads();
    if (tid < C) {
        float s = 0.f;
#pragma unroll
        for (int sub = 0; sub < 32; sub++) s += part[sub * C + tid];
        colsum[tid] = s;
        invcol[tid] = 1.0f / (s + EPSF);
    }
    __syncthreads();

    // ---- pass 3: fused S1/S2 (packed, normalize on the fly)
    {
        float icn = invcol[gc];
        u64t s1x = 0, s1z = 0, s2x = 0, s2z = 0;
#pragma unroll
        for (int it = 0; it < ITER; it++) {
            int i = rep + it * REPS4;
            float cf = r[i * C + gc] * icn;
            u64t cf2 = f2pack(cf, cf);
            s1x = f2fma(cf2, vx[it], s1x);
            s1z = f2fma(cf2, vz[it], s1z);
            s2x = f2fma(cf2, f2mul(vx[it], vx[it]), s2x);
            s2z = f2fma(cf2, f2mul(vz[it], vz[it]), s2z);
        }
        ((ulonglong2*)part)[rep * 64 + g] = make_ulonglong2(s1x, s1z);
        ((ulonglong2*)part)[(REPS4 + rep) * 64 + g] = make_ulonglong2(s2x, s2z);
    }
    __syncthreads();
    if (tid < CP) {
        float s1 = 0.f, s2 = 0.f;
#pragma unroll
        for (int rr = 0; rr < REPS4; rr++) {
            s1 += part[rr * CP + tid];
            s2 += part[(REPS4 + rr) * CP + tid];
        }
        mu[tid] = s1;
        float cs = colsum[tid >> 4];
        float rho = cs / (cs + EPSF);
        sig[tid] = fmaxf(s2 - s1 * s1 * (2.0f - rho), 0.0f) + EPSF;
    }
    __syncthreads();

    if (tid < C) {
        float ls = 0.f;
#pragma unroll
        for (int p = 0; p < 16; p++) ls += logf(sig[tid * 16 + p]);
        float cost = colsum[tid] * (16.0f * bu[tid] + 0.5f * ls);
        a_out_g[n * C + tid] = 1.0f / (1.0f + expf(-LAMF * (ba[tid] - cost)));
    }
    {
        float4* po4 = (float4*)(pose_out + (size_t)n * CP);
        for (int t = tid; t < 64; t += THREADS) po4[t] = ((const float4*)mu)[t];
    }
}

// =====================================================================
// class caps: votes+mu0 fused (fixed (c,p)-ownership), v in L2
// =====================================================================
__global__ void __launch_bounds__(1024) class_kernel(
    const float* __restrict__ wc, const float* __restrict__ buc,
    const float* __restrict__ bac, float* __restrict__ out)
{
    constexpr int N = 400, C = 10, CP = 160, T = 1024, REPS = 6;
    __shared__ float a[N];
    __shared__ float wa[N];
    __shared__ float r[N * C];
    __shared__ __align__(16) float mu[CP];
    __shared__ float sig[CP];
    __shared__ float part[2 * REPS * CP];
    __shared__ __align__(16) float partA[25 * CP];
    __shared__ float colsum[C];
    __shared__ float sA;

    const int b = blockIdx.x;
    const int tid = threadIdx.x;
    const float* pose = d_pose2 + (size_t)b * N * 16;
    float* v = d_vbuf + (size_t)b * N * C * 16;

    for (int i = tid; i < N; i += T) a[i] = d_a2[b * N + i];
    __syncthreads();

    if (tid < 32) {
        float s = 0.f;
        for (int i = tid; i < N; i += 32) s += a[i];
#pragma unroll
        for (int o = 16; o; o >>= 1) s += __shfl_xor_sync(0xffffffffu, s, o);
        if (tid == 0) sA = s;
    }
    __syncthreads();
    {
        float denom = sA + EPSF * (float)(C * C);
        for (int i = tid; i < N; i += T) wa[i] = a[i] / denom;
    }
    __syncthreads();

    {
        const int g = tid % 40, rep = tid / 40;
        if (rep < 25) {
            const int gc = g >> 2, gp = g & 3;
            float4 acc = make_float4(0.f, 0.f, 0.f, 0.f);
#pragma unroll
            for (int it = 0; it < 16; it++) {
                int i = rep + it * 25;
                float4 pv = ((const float4*)pose)[i * 4 + gp];
                const float4* wp4 = (const float4*)(wc + ((size_t)((i & 15) * 10 + gc)) * 16);
                float4 w0 = wp4[0], w1 = wp4[1], w2 = wp4[2], w3 = wp4[3];
                float4 o;
                o.x = pv.x * w0.x + pv.y * w1.x + pv.z * w2.x + pv.w * w3.x;
                o.y = pv.x * w0.y + pv.y * w1.y + pv.z * w2.y + pv.w * w3.y;
                o.z = pv.x * w0.z + pv.y * w1.z + pv.z * w2.z + pv.w * w3.z;
                o.w = pv.x * w0.w + pv.y * w1.w + pv.z * w2.w + pv.w * w3.w;
                if (gp == 0) {
                    o.x += (float)(i / 80) * 0.2f;
                    o.y += (float)((i / 16) % 5) * 0.2f;
                }
                *(float4*)(v + (i * C + gc) * 16 + gp * 4) = o;
                float wi = wa[i];
                acc.x += wi * o.x; acc.y += wi * o.y;
                acc.z += wi * o.z; acc.w += wi * o.w;
            }
            ((float4*)partA)[rep * 40 + g] = acc;
        }
    }
    __syncthreads();
    if (tid < CP) {
        float s = 0.f;
#pragma unroll
        for (int rr = 0; rr < 25; rr++) s += partA[rr * CP + tid];
        mu[tid] = s;
    }
    __syncthreads();

    for (int t = tid; t < N * C * 4; t += T) {
        int pair = t >> 2, ch = t & 3;
        int c = pair % C;
        float4 vv = *(const float4*)(v + pair * 16 + ch * 4);
        float4 mm = *(const float4*)(mu + c * 16 + ch * 4);
        float dx = vv.x - mm.x, dy = vv.y - mm.y, dz = vv.z - mm.z, dw = vv.w - mm.w;
        float d = dx * dx + dy * dy + dz * dz + dw * dw;
        d += __shfl_xor_sync(0xffffffffu, d, 1);
        d += __shfl_xor_sync(0xffffffffu, d, 2);
        if (ch == 0) r[pair] = 1.0f / (d + EPSF);
    }
    __syncthreads();

    for (int i = tid; i < N; i += T) {
        float s = 0.f;
#pragma unroll
        for (int c = 0; c < C; c++) s += r[i * C + c];
        wa[i] = 1.0f / (s + EPSF);
    }
    __syncthreads();

    for (int t = tid; t < N * C; t += T) {
        int i = t / C;
        float val = r[t] * wa[i];
        r[t] = val * val * a[i];
    }
    __syncthreads();

    for (int t = tid; t < 32 * C; t += T) {
        int sub = t / C, c = t % C;
        float s = 0.f;
        for (int i = sub; i < N; i += 32) s += r[i * C + c];
        part[t] = s;
    }
    __syncthreads();
    if (tid < C) {
        float s = 0.f;
#pragma unroll
        for (int sub = 0; sub < 32; sub++) s += part[sub * C + tid];
        colsum[tid] = s;
    }
    __syncthreads();

    for (int t = tid; t < N * C; t += T) r[t] /= (colsum[t % C] + EPSF);
    __syncthreads();

    {
        int rep = tid / CP, t2 = tid % CP;
        if (rep < REPS) {
            int c = t2 / 16, pr = t2 & 15;
            float s1 = 0.f, s2 = 0.f;
            for (int i = rep; i < N; i += REPS) {
                float cf = r[i * C + c];
                float vv = v[(i * C + c) * 16 + pr];
                s1 += cf * vv;
                s2 += cf * vv * vv;
            }
            part[rep * CP + t2] = s1;
            part[(REPS + rep) * CP + t2] = s2;
        }
    }
    __syncthreads();
    if (tid < CP) {
        float s1 = 0.f, s2 = 0.f;
#pragma unroll
        for (int rr = 0; rr < REPS; rr++) {
            s1 += part[rr * CP + tid];
            s2 += part[(REPS + rr) * CP + tid];
        }
        int c = tid / 16;
        float cs = colsum[c];
        float rho = cs / (cs + EPSF);
        sig[tid] = fmaxf(s2 - s1 * s1 * (2.0f - rho), 0.0f) + EPSF;
    }
    __syncthreads();

    if (tid < C) {
        float ls = 0.f;
#pragma unroll
        for (int p = 0; p < 16; p++) ls += logf(sig[tid * 16 + p]);
        float cost = colsum[tid] * (16.0f * buc[tid] + 0.5f * ls);
        out[b * C + tid] = 1.0f / (1.0f + expf(-LAMF * (bac[tid] - cost)));
    }
}

// ---------------- launch ----------------
extern "C" void kernel_launch(void* const* d_in, const int* in_sizes, int n_in,
                              void* d_out, int out_size)
{
    const float* x        = (const float*)d_in[0];
    const float* conv1_w  = (const float*)d_in[1];
    const float* conv1_b  = (const float*)d_in[2];
    const float* bn_g     = (const float*)d_in[3];
    const float* bn_b     = (const float*)d_in[4];
    const float* bn_mean  = (const float*)d_in[5];
    const float* bn_var   = (const float*)d_in[6];
    const float* ppose_w  = (const float*)d_in[7];
    const float* ppose_b  = (const float*)d_in[8];
    const float* pa_w     = (const float*)d_in[9];
    const float* pa_b     = (const float*)d_in[10];
    const float* w1       = (const float*)d_in[11];
    const float* bu1      = (const float*)d_in[12];
    const float* ba1      = (const float*)d_in[13];
    const float* w2       = (const float*)d_in[14];
    const float* bu2      = (const float*)d_in[15];
    const float* ba2      = (const float*)d_in[16];
    const float* wc       = (const float*)d_in[17];
    const float* buc      = (const float*)d_in[18];
    const float* bac      = (const float*)d_in[19];
    float* out = (float*)d_out;

    float *ppose, *aprim, *pose1, *a1, *pose2, *a2;
    cudaGetSymbolAddress((void**)&ppose, d_pose_prim);
    cudaGetSymbolAddress((void**)&aprim, d_a_prim);
    cudaGetSymbolAddress((void**)&pose1, d_pose1);
    cudaGetSymbolAddress((void**)&a1, d_a1);
    cudaGetSymbolAddress((void**)&pose2, d_pose2);
    cudaGetSymbolAddress((void**)&a2, d_a2);

    convprim_kernel<<<1024, 256>>>(x, conv1_w, conv1_b, bn_g, bn_b, bn_mean, bn_var,
                                   ppose_w, ppose_b, pa_w, pa_b);
    caps_kernel<72, 8, 16, 7, 16, 2><<<3136, 768>>>(
        ppose, aprim, w1, bu1, ba1, pose1, a1);
    caps_kernel<144, 16, 16, 5, 7, 1><<<1600, 768>>>(
        pose1, a1, w2, bu2, ba2, pose2, a2);
    class_kernel<<<64, 1024>>>(wc, buc, bac, out);
}

// round 15
// speedup vs baseline: 3.3701x; 1.7186x over previous
#include <cuda_runtime.h>
#include <math.h>

#define EPSF 1e-8f
#define LAMF 1e-3f

// ---------------- packed f32x2 helpers (Blackwell) ----------------
typedef unsigned long long u64t;
__device__ __forceinline__ u64t f2pack(float lo, float hi) {
    u64t r; asm("mov.b64 %0, {%1, %2};" : "=l"(r) : "f"(lo), "f"(hi)); return r;
}
__device__ __forceinline__ float2 f2unpack(u64t v) {
    float2 f; asm("mov.b64 {%0, %1}, %2;" : "=f"(f.x), "=f"(f.y) : "l"(v)); return f;
}
__device__ __forceinline__ u64t f2fma(u64t a, u64t b, u64t c) {
    u64t d; asm("fma.rn.f32x2 %0, %1, %2, %3;" : "=l"(d) : "l"(a), "l"(b), "l"(c)); return d;
}
__device__ __forceinline__ u64t f2mul(u64t a, u64t b) {
    u64t d; asm("mul.rn.f32x2 %0, %1, %2;" : "=l"(d) : "l"(a), "l"(b)); return d;
}
__device__ __forceinline__ u64t f2add(u64t a, u64t b) {
    u64t d; asm("add.rn.f32x2 %0, %1, %2;" : "=l"(d) : "l"(a), "l"(b)); return d;
}

// ---------------- static device scratch ----------------
__device__ float d_pose_prim[64 * 16 * 16 * 128];  // (b,h,w,8,16)
__device__ float d_a_prim[64 * 16 * 16 * 8];       // (b,h,w,8)
__device__ float d_pose1[64 * 7 * 7 * 16 * 16];
__device__ float d_a1[64 * 7 * 7 * 16];
__device__ float d_pose2[64 * 5 * 5 * 16 * 16];
__device__ float d_a2[64 * 5 * 5 * 16];
__device__ float d_vbuf[4096000];                  // class votes only

// =====================================================================
// fused conv5x5s2 + BN + ReLU + primary caps
// =====================================================================
__global__ void __launch_bounds__(256) convprim_kernel(
    const float* __restrict__ x, const float* __restrict__ w,
    const float* __restrict__ bconv, const float* __restrict__ g,
    const float* __restrict__ bb, const float* __restrict__ mean,
    const float* __restrict__ var,
    const float* __restrict__ pw, const float* __restrict__ pb,
    const float* __restrict__ aw, const float* __restrict__ ab)
{
    __shared__ float xs[160];
    __shared__ float wconv[1600];
    __shared__ __align__(16) float yv[1024];
    __shared__ __align__(16) float wp_s[128 * 68];
    __shared__ __align__(16) float wa_s[8 * 68];
    __shared__ float bnsc[64], bnbi[64];

    const int tid = threadIdx.x;
    const int blk = blockIdx.x;
    const int b = blk >> 4, oh = blk & 15;

    for (int t = tid; t < 160; t += 256) {
        int kh = t >> 5, iw = t & 31;
        int ih = oh * 2 - 2 + kh;
        xs[t] = (ih >= 0 && ih < 32) ? x[b * 1024 + ih * 32 + iw] : 0.0f;
    }
    for (int t = tid; t < 1600; t += 256) wconv[t] = w[t];
    for (int t = tid; t < 128 * 64; t += 256) {
        int o = t >> 6, c = t & 63;
        wp_s[o * 68 + c] = pw[t];
    }
    for (int t = tid; t < 8 * 64; t += 256) {
        int o = t >> 6, c = t & 63;
        wa_s[o * 68 + c] = aw[t];
    }
    if (tid < 64) {
        float sc = g[tid] * rsqrtf(var[tid] + 1e-3f);
        bnsc[tid] = sc;
        bnbi[tid] = bb[tid] - mean[tid] * sc;
    }
    __syncthreads();

    for (int t = tid; t < 1024; t += 256) {
        int co = t & 63, ow = t >> 6;
        float acc = bconv[co];
        const float* wr = wconv + co * 25;
#pragma unroll
        for (int kh = 0; kh < 5; kh++) {
#pragma unroll
            for (int kw = 0; kw < 5; kw++) {
                int iw = ow * 2 - 2 + kw;
                if (iw >= 0 && iw < 32)
                    acc += xs[kh * 32 + iw] * wr[kh * 5 + kw];
            }
        }
        yv[ow * 64 + co] = fmaxf(acc * bnsc[co] + bnbi[co], 0.0f);
    }
    __syncthreads();

    for (int t = tid; t < 16 * 136; t += 256) {
        int pos = t / 136, o = t % 136;
        const float4* y4 = (const float4*)(yv + pos * 64);
        int pg = (blk << 4) + pos;
        if (o < 128) {
            const float4* w4 = (const float4*)(wp_s + o * 68);
            float4 a4 = make_float4(0.f, 0.f, 0.f, 0.f);
#pragma unroll
            for (int j = 0; j < 16; j++) {
                float4 yy = y4[j], ww = w4[j];
                a4.x += yy.x * ww.x; a4.y += yy.y * ww.y;
                a4.z += yy.z * ww.z; a4.w += yy.w * ww.w;
            }
            d_pose_prim[pg * 128 + o] = pb[o] + a4.x + a4.y + a4.z + a4.w;
        } else {
            int o2 = o - 128;
            const float4* w4 = (const float4*)(wa_s + o2 * 68);
            float4 a4 = make_float4(0.f, 0.f, 0.f, 0.f);
#pragma unroll
            for (int j = 0; j < 16; j++) {
                float4 yy = y4[j], ww = w4[j];
                a4.x += yy.x * ww.x; a4.y += yy.y * ww.y;
                a4.z += yy.z * ww.z; a4.w += yy.w * ww.w;
            }
            float acc = ab[o2] + a4.x + a4.y + a4.z + a4.w;
            d_a_prim[pg * 8 + o2] = 1.0f / (1.0f + expf(-acc));
        }
    }
}

// =====================================================================
// conv caps layer: register-resident votes, packed f32x2 math.
// 512 threads = exactly one RF-full block/SM (the feasible optimum).
// =====================================================================
template <int N, int Bi, int C, int OHW, int IHW, int STRIDE>
__global__ void __launch_bounds__(512) caps_kernel(
    const float* __restrict__ pose_in, const float* __restrict__ a_in,
    const float* __restrict__ W, const float* __restrict__ bu,
    const float* __restrict__ ba,
    float* __restrict__ pose_out, float* __restrict__ a_out_g)
{
    static_assert(C == 16, "caps path assumes C==16");
    constexpr int THREADS = 512;
    constexpr int CP = 256;
    constexpr int REPS4 = 8;
    constexpr int ITER = N / REPS4;
    static_assert(N % REPS4 == 0, "N divisible");

    __shared__ __align__(16) float pp[N * 16];
    __shared__ float a[N];
    __shared__ float wa[N];
    __shared__ float r[N * C];
    __shared__ __align__(16) float mu[CP];
    __shared__ float sig[CP];
    __shared__ __align__(16) float part[2 * REPS4 * CP];
    __shared__ float colsum[C];
    __shared__ float invcol[C];
    __shared__ float sA;

    const int tid = threadIdx.x;
    const int n = blockIdx.x;
    const int b = n / (OHW * OHW);
    const int rem = n % (OHW * OHW);
    const int oh = rem / OHW, ow = rem % OHW;

    {
        float4* pp4s = (float4*)pp;
        for (int idx = tid; idx < N * 4; idx += THREADS) {
            int i = idx >> 2, q = idx & 3;
            int kh = i / (3 * Bi), kw = (i / Bi) % 3, bi = i % Bi;
            int ih = oh * STRIDE + kh, iw = ow * STRIDE + kw;
            pp4s[idx] = ((const float4*)pose_in)[(((b * IHW + ih) * IHW + iw) * Bi + bi) * 4 + q];
        }
    }
    for (int i = tid; i < N; i += THREADS) {
        int kh = i / (3 * Bi), kw = (i / Bi) % 3, bi = i % Bi;
        int ih = oh * STRIDE + kh, iw = ow * STRIDE + kw;
        a[i] = a_in[((b * IHW + ih) * IHW + iw) * Bi + bi];
    }
    __syncthreads();

    if (tid < 32) {
        float s = 0.f;
        for (int i = tid; i < N; i += 32) s += a[i];
#pragma unroll
        for (int o = 16; o; o >>= 1) s += __shfl_xor_sync(0xffffffffu, s, o);
        if (tid == 0) sA = s;
    }
    __syncthreads();
    {
        float denom = sA + EPSF * (float)(C * C);
        for (int i = tid; i < N; i += THREADS) wa[i] = a[i] / denom;
    }
    __syncthreads();

    const int g = tid & 63, rep = tid >> 6;
    const int gc = g >> 2, gp = g & 3;

    u64t vx[ITER], vz[ITER];   // packed votes: (x,y) and (z,w)

    // ---- pass 1: votes (packed) + mu0 partials
    {
        const float4* pp4 = (const float4*)pp;
        const ulonglong2* W2 = (const ulonglong2*)W;
        u64t accx = 0, accz = 0;
#pragma unroll
        for (int it = 0; it < ITER; it++) {
            int i = rep + it * REPS4;
            float4 pv = pp4[i * 4 + gp];
            u64t p0 = f2pack(pv.x, pv.x);
            u64t p1 = f2pack(pv.y, pv.y);
            u64t p2 = f2pack(pv.z, pv.z);
            u64t p3 = f2pack(pv.w, pv.w);
            const ulonglong2* wr = W2 + (size_t)(i * C + gc) * 4;
            ulonglong2 q0 = wr[0], q1 = wr[1], q2 = wr[2], q3 = wr[3];
            u64t oxy = f2mul(p0, q0.x);
            oxy = f2fma(p1, q1.x, oxy);
            oxy = f2fma(p2, q2.x, oxy);
            oxy = f2fma(p3, q3.x, oxy);
            u64t ozw = f2mul(p0, q0.y);
            ozw = f2fma(p1, q1.y, ozw);
            ozw = f2fma(p2, q2.y, ozw);
            ozw = f2fma(p3, q3.y, ozw);
            vx[it] = oxy; vz[it] = ozw;
            u64t wi2 = f2pack(wa[i], wa[i]);
            accx = f2fma(wi2, oxy, accx);
            accz = f2fma(wi2, ozw, accz);
        }
        ((ulonglong2*)part)[rep * 64 + g] = make_ulonglong2(accx, accz);
    }
    __syncthreads();
    if (tid < CP) {
        float s = 0.f;
#pragma unroll
        for (int rr = 0; rr < REPS4; rr++) s += part[rr * CP + tid];
        mu[tid] = s;
    }
    __syncthreads();

    // ---- pass 2: dist -> inv (packed, from registers)
    {
        float4 mm = ((const float4*)mu)[gc * 4 + gp];
        u64t nmx = f2pack(-mm.x, -mm.y);
        u64t nmz = f2pack(-mm.z, -mm.w);
#pragma unroll
        for (int it = 0; it < ITER; it++) {
            int i = rep + it * REPS4;
            u64t t1 = f2add(vx[it], nmx);
            u64t t2 = f2add(vz[it], nmz);
            u64t u = f2fma(t2, t2, f2mul(t1, t1));
            float2 uf = f2unpack(u);
            float d = uf.x + uf.y;
            d += __shfl_xor_sync(0xffffffffu, d, 1);
            d += __shfl_xor_sync(0xffffffffu, d, 2);
            if (gp == 0) r[i * C + gc] = 1.0f / (d + EPSF);
        }
    }
    __syncthreads();

    // ---- rowsum over C via 16-lane shuffle
    for (int t = tid; t < N * 16; t += THREADS) {
        int i = t >> 4, c = t & 15;
        float s = r[i * 16 + c];
        s += __shfl_xor_sync(0xffffffffu, s, 1);
        s += __shfl_xor_sync(0xffffffffu, s, 2);
        s += __shfl_xor_sync(0xffffffffu, s, 4);
        s += __shfl_xor_sync(0xffffffffu, s, 8);
        if (c == 0) wa[i] = 1.0f / (s + EPSF);
    }
    __syncthreads();

    // ---- fused coeff^2*a + colsum partials
    for (int t = tid; t < 32 * C; t += THREADS) {
        int sub = t >> 4, c = t & 15;
        float s = 0.f;
        for (int i = sub; i < N; i += 32) {
            float val = r[i * C + c] * wa[i];
            val = val * val * a[i];
            r[i * C + c] = val;
            s += val;
        }
        part[t] = s;
    }
    __syncthreads();
    if (tid < C) {
        float s = 0.f;
#pragma unroll
        for (int sub = 0; sub < 32; sub++) s += part[sub * C + tid];
        colsum[tid] = s;
        invcol[tid] = 1.0f / (s + EPSF);
    }
    __syncthreads();

    // ---- pass 3: fused S1/S2 (packed, normalize on the fly)
    {
        float icn = invcol[gc];
        u64t s1x = 0, s1z = 0, s2x = 0, s2z = 0;
#pragma unroll
        for (int it = 0; it < ITER; it++) {
            int i = rep + it * REPS4;
            float cf = r[i * C + gc] * icn;
            u64t cf2 = f2pack(cf, cf);
            s1x = f2fma(cf2, vx[it], s1x);
            s1z = f2fma(cf2, vz[it], s1z);
            s2x = f2fma(cf2, f2mul(vx[it], vx[it]), s2x);
            s2z = f2fma(cf2, f2mul(vz[it], vz[it]), s2z);
        }
        ((ulonglong2*)part)[rep * 64 + g] = make_ulonglong2(s1x, s1z);
        ((ulonglong2*)part)[(REPS4 + rep) * 64 + g] = make_ulonglong2(s2x, s2z);
    }
    __syncthreads();
    if (tid < CP) {
        float s1 = 0.f, s2 = 0.f;
#pragma unroll
        for (int rr = 0; rr < REPS4; rr++) {
            s1 += part[rr * CP + tid];
            s2 += part[(REPS4 + rr) * CP + tid];
        }
        mu[tid] = s1;
        float cs = colsum[tid >> 4];
        float rho = cs / (cs + EPSF);
        sig[tid] = fmaxf(s2 - s1 * s1 * (2.0f - rho), 0.0f) + EPSF;
    }
    __syncthreads();

    if (tid < C) {
        float ls = 0.f;
#pragma unroll
        for (int p = 0; p < 16; p++) ls += logf(sig[tid * 16 + p]);
        float cost = colsum[tid] * (16.0f * bu[tid] + 0.5f * ls);
        a_out_g[n * C + tid] = 1.0f / (1.0f + expf(-LAMF * (ba[tid] - cost)));
    }
    {
        float4* po4 = (float4*)(pose_out + (size_t)n * CP);
        for (int t = tid; t < 64; t += THREADS) po4[t] = ((const float4*)mu)[t];
    }
}

// =====================================================================
// class caps: votes+mu0 fused (fixed (c,p)-ownership), v in L2
// =====================================================================
__global__ void __launch_bounds__(1024) class_kernel(
    const float* __restrict__ wc, const float* __restrict__ buc,
    const float* __restrict__ bac, float* __restrict__ out)
{
    constexpr int N = 400, C = 10, CP = 160, T = 1024, REPS = 6;
    __shared__ float a[N];
    __shared__ float wa[N];
    __shared__ float r[N * C];
    __shared__ __align__(16) float mu[CP];
    __shared__ float sig[CP];
    __shared__ float part[2 * REPS * CP];
    __shared__ __align__(16) float partA[25 * CP];
    __shared__ float colsum[C];
    __shared__ float colinv[C];
    __shared__ float sA;

    const int b = blockIdx.x;
    const int tid = threadIdx.x;
    const float* pose = d_pose2 + (size_t)b * N * 16;
    float* v = d_vbuf + (size_t)b * N * C * 16;

    for (int i = tid; i < N; i += T) a[i] = d_a2[b * N + i];
    __syncthreads();

    if (tid < 32) {
        float s = 0.f;
        for (int i = tid; i < N; i += 32) s += a[i];
#pragma unroll
        for (int o = 16; o; o >>= 1) s += __shfl_xor_sync(0xffffffffu, s, o);
        if (tid == 0) sA = s;
    }
    __syncthreads();
    {
        float denom = sA + EPSF * (float)(C * C);
        for (int i = tid; i < N; i += T) wa[i] = a[i] / denom;
    }
    __syncthreads();

    {
        const int g = tid % 40, rep = tid / 40;
        if (rep < 25) {
            const int gc = g >> 2, gp = g & 3;
            float4 acc = make_float4(0.f, 0.f, 0.f, 0.f);
#pragma unroll
            for (int it = 0; it < 16; it++) {
                int i = rep + it * 25;
                float4 pv = ((const float4*)pose)[i * 4 + gp];
                const float4* wp4 = (const float4*)(wc + ((size_t)((i & 15) * 10 + gc)) * 16);
                float4 w0 = wp4[0], w1 = wp4[1], w2 = wp4[2], w3 = wp4[3];
                float4 o;
                o.x = pv.x * w0.x + pv.y * w1.x + pv.z * w2.x + pv.w * w3.x;
                o.y = pv.x * w0.y + pv.y * w1.y + pv.z * w2.y + pv.w * w3.y;
                o.z = pv.x * w0.z + pv.y * w1.z + pv.z * w2.z + pv.w * w3.z;
                o.w = pv.x * w0.w + pv.y * w1.w + pv.z * w2.w + pv.w * w3.w;
                if (gp == 0) {
                    o.x += (float)(i / 80) * 0.2f;
                    o.y += (float)((i / 16) % 5) * 0.2f;
                }
                *(float4*)(v + (i * C + gc) * 16 + gp * 4) = o;
                float wi = wa[i];
                acc.x += wi * o.x; acc.y += wi * o.y;
                acc.z += wi * o.z; acc.w += wi * o.w;
            }
            ((float4*)partA)[rep * 40 + g] = acc;
        }
    }
    __syncthreads();
    if (tid < CP) {
        float s = 0.f;
#pragma unroll
        for (int rr = 0; rr < 25; rr++) s += partA[rr * CP + tid];
        mu[tid] = s;
    }
    __syncthreads();

    for (int t = tid; t < N * C * 4; t += T) {
        int pair = t >> 2, ch = t & 3;
        int c = pair % C;
        float4 vv = *(const float4*)(v + pair * 16 + ch * 4);
        float4 mm = *(const float4*)(mu + c * 16 + ch * 4);
        float dx = vv.x - mm.x, dy = vv.y - mm.y, dz = vv.z - mm.z, dw = vv.w - mm.w;
        float d = dx * dx + dy * dy + dz * dz + dw * dw;
        d += __shfl_xor_sync(0xffffffffu, d, 1);
        d += __shfl_xor_sync(0xffffffffu, d, 2);
        if (ch == 0) r[pair] = 1.0f / (d + EPSF);
    }
    __syncthreads();

    for (int i = tid; i < N; i += T) {
        float s = 0.f;
#pragma unroll
        for (int c = 0; c < C; c++) s += r[i * C + c];
        wa[i] = 1.0f / (s + EPSF);
    }
    __syncthreads();

    for (int t = tid; t < N * C; t += T) {
        int i = t / C;
        float val = r[t] * wa[i];
        r[t] = val * val * a[i];
    }
    __syncthreads();

    for (int t = tid; t < 32 * C; t += T) {
        int sub = t / C, c = t % C;
        float s = 0.f;
        for (int i = sub; i < N; i += 32) s += r[i * C + c];
        part[t] = s;
    }
    __syncthreads();
    if (tid < C) {
        float s = 0.f;
#pragma unroll
        for (int sub = 0; sub < 32; sub++) s += part[sub * C + tid];
        colsum[tid] = s;
        colinv[tid] = 1.0f / (s + EPSF);
    }
    __syncthreads();

    // normalize via precomputed inverse (FMUL instead of FDIV)
    for (int t = tid; t < N * C; t += T) r[t] *= colinv[t % C];
    __syncthreads();

    {
        int rep = tid / CP, t2 = tid % CP;
        if (rep < REPS) {
            int c = t2 / 16, pr = t2 & 15;
            float s1 = 0.f, s2 = 0.f;
            for (int i = rep; i < N; i += REPS) {
                float cf = r[i * C + c];
                float vv = v[(i * C + c) * 16 + pr];
                s1 += cf * vv;
                s2 += cf * vv * vv;
            }
            part[rep * CP + t2] = s1;
            part[(REPS + rep) * CP + t2] = s2;
        }
    }
    __syncthreads();
    if (tid < CP) {
        float s1 = 0.f, s2 = 0.f;
#pragma unroll
        for (int rr = 0; rr < REPS; rr++) {
            s1 += part[rr * CP + tid];
            s2 += part[(REPS + rr) * CP + tid];
        }
        int c = tid / 16;
        float cs = colsum[c];
        float rho = cs / (cs + EPSF);
        sig[tid] = fmaxf(s2 - s1 * s1 * (2.0f - rho), 0.0f) + EPSF;
    }
    __syncthreads();

    if (tid < C) {
        float ls = 0.f;
#pragma unroll
        for (int p = 0; p < 16; p++) ls += logf(sig[tid * 16 + p]);
        float cost = colsum[tid] * (16.0f * buc[tid] + 0.5f * ls);
        out[b * C + tid] = 1.0f / (1.0f + expf(-LAMF * (bac[tid] - cost)));
    }
}

// ---------------- launch ----------------
extern "C" void kernel_launch(void* const* d_in, const int* in_sizes, int n_in,
                              void* d_out, int out_size)
{
    const float* x        = (const float*)d_in[0];
    const float* conv1_w  = (const float*)d_in[1];
    const float* conv1_b  = (const float*)d_in[2];
    const float* bn_g     = (const float*)d_in[3];
    const float* bn_b     = (const float*)d_in[4];
    const float* bn_mean  = (const float*)d_in[5];
    const float* bn_var   = (const float*)d_in[6];
    const float* ppose_w  = (const float*)d_in[7];
    const float* ppose_b  = (const float*)d_in[8];
    const float* pa_w     = (const float*)d_in[9];
    const float* pa_b     = (const float*)d_in[10];
    const float* w1       = (const float*)d_in[11];
    const float* bu1      = (const float*)d_in[12];
    const float* ba1      = (const float*)d_in[13];
    const float* w2       = (const float*)d_in[14];
    const float* bu2      = (const float*)d_in[15];
    const float* ba2      = (const float*)d_in[16];
    const float* wc       = (const float*)d_in[17];
    const float* buc      = (const float*)d_in[18];
    const float* bac      = (const float*)d_in[19];
    float* out = (float*)d_out;

    float *ppose, *aprim, *pose1, *a1, *pose2, *a2;
    cudaGetSymbolAddress((void**)&ppose, d_pose_prim);
    cudaGetSymbolAddress((void**)&aprim, d_a_prim);
    cudaGetSymbolAddress((void**)&pose1, d_pose1);
    cudaGetSymbolAddress((void**)&a1, d_a1);
    cudaGetSymbolAddress((void**)&pose2, d_pose2);
    cudaGetSymbolAddress((void**)&a2, d_a2);

    convprim_kernel<<<1024, 256>>>(x, conv1_w, conv1_b, bn_g, bn_b, bn_mean, bn_var,
                                   ppose_w, ppose_b, pa_w, pa_b);
    caps_kernel<72, 8, 16, 7, 16, 2><<<3136, 512>>>(
        ppose, aprim, w1, bu1, ba1, pose1, a1);
    caps_kernel<144, 16, 16, 5, 7, 1><<<1600, 512>>>(
        pose1, a1, w2, bu2, ba2, pose2, a2);
    class_kernel<<<64, 1024>>>(wc, buc, bac, out);
}